// round 2
// baseline (speedup 1.0000x reference)
#include <cuda_runtime.h>
#include <math.h>
#include <stdint.h>

// Shapes fixed by the problem definition.
#define Bv 4
#define Tv 2048
#define Dv 384
#define Hv 192
#define MROWS 16   // rows per MLP block (4 warps x 4 rows)
#define PPB 8      // output positions per expansion block
#define NTHR 128

// Scratch (no allocs allowed): batch-0 durations, their cumsum, total.
__device__ float g_dur[Tv];
__device__ int   g_cum[Tv];
__device__ int   g_total;

#define FMA_F32X2(d, a, b, c) \
    asm("fma.rn.f32x2 %0, %1, %2, %3;" : "=l"(d) : "l"(a), "l"(b), "l"(c))
#define PACK_DUP(out, v) \
    asm("mov.b64 %0, {%1, %1};" : "=l"(out) : "r"(v))
#define UNPACK2(lo, hi, in) \
    asm("mov.b64 {%0, %1}, %2;" : "=r"(lo), "=r"(hi) : "l"(in))

__device__ __forceinline__ float duration_of(float z) {
    // softplus -> clamp to MIN_DUR=8 -> round (nearest-even, matching jnp.round)
    float sp = (z > 20.f) ? z : log1pf(expf(z));
    return rintf(fmaxf(sp, 8.f));
}

// One block (128 thr, 4 warps) computes durations for MROWS=16 rows at row0.
// Warp w owns rows 4w..4w+3. Lane owns 3 hidden j-pairs jp = lane + 32m
// (j = 2jp), so w1 pairs load as contiguous LDG.64. Accumulation uses packed
// fma.rn.f32x2 (2 FMA/instr). x tile lives in smem, loaded once (1 barrier).
__device__ __forceinline__ void mlp_block(
    const float* __restrict__ x, const float* __restrict__ w1,
    const float* __restrict__ b1, const float* __restrict__ w2,
    const float* __restrict__ b2, int row0,
    float* s_x, float* __restrict__ dur_base)
{
    const int tid  = threadIdx.x;
    const int lane = tid & 31;
    const int warp = tid >> 5;
    const int rb   = warp * 4;

    // Load x tile [MROWS][Dv] coalesced as float4 (once).
    {
        const float4* __restrict__ x4 = (const float4*)(x + (long)row0 * Dv);
        float4* s4 = (float4*)s_x;
        const int n4 = MROWS * Dv / 4;          // 1536
#pragma unroll
        for (int i = tid; i < n4; i += NTHR) s4[i] = x4[i];
    }
    __syncthreads();

    uint64_t acc[4][3];
#pragma unroll
    for (int r = 0; r < 4; ++r)
#pragma unroll
        for (int m = 0; m < 3; ++m) acc[r][m] = 0ull;

    const int jp0 = lane;                        // j-pair base
    for (int k0 = 0; k0 < Dv; k0 += 4) {
        float xa[4][4];
#pragma unroll
        for (int r = 0; r < 4; ++r)
            *(float4*)&xa[r][0] = *(const float4*)(s_x + (rb + r) * Dv + k0);
#pragma unroll
        for (int kk = 0; kk < 4; ++kk) {
            uint64_t xd[4];
#pragma unroll
            for (int r = 0; r < 4; ++r) {
                float xv = xa[r][kk];
                PACK_DUP(xd[r], __float_as_uint(xv));
            }
#pragma unroll
            for (int m = 0; m < 3; ++m) {
                uint64_t wv = *(const uint64_t*)(w1 + (long)(k0 + kk) * Hv
                                                 + 2 * (jp0 + 32 * m));
#pragma unroll
                for (int r = 0; r < 4; ++r)
                    FMA_F32X2(acc[r][m], xd[r], wv, acc[r][m]);
            }
        }
    }

    // Epilogue: bias, relu, dot with w2, warp-reduce per row.
    float bz = b2[0];
#pragma unroll
    for (int r = 0; r < 4; ++r) {
        float p = 0.f;
#pragma unroll
        for (int m = 0; m < 3; ++m) {
            uint32_t lo, hi;
            UNPACK2(lo, hi, acc[r][m]);
            int jp = jp0 + 32 * m;
            float2 bb = *(const float2*)(b1 + 2 * jp);
            float2 ww = *(const float2*)(w2 + 2 * jp);
            p += fmaxf(__uint_as_float(lo) + bb.x, 0.f) * ww.x;
            p += fmaxf(__uint_as_float(hi) + bb.y, 0.f) * ww.y;
        }
#pragma unroll
        for (int off = 16; off > 0; off >>= 1)
            p += __shfl_xor_sync(0xffffffffu, p, off);
        if (lane == 0)
            dur_base[row0 + rb + r] = duration_of(p + bz);
    }
}

// K1: durations for batch 0 (rows 0..Tv) -> g_dur
__global__ __launch_bounds__(NTHR)
void mlp_kernel(const float* __restrict__ x, const float* __restrict__ w1,
                const float* __restrict__ b1, const float* __restrict__ w2,
                const float* __restrict__ b2)
{
    __shared__ float s_x[MROWS * Dv];
    mlp_block(x, w1, b1, w2, b2, blockIdx.x * MROWS, s_x, g_dur);
}

// K2: single-block inclusive scan of (int)g_dur -> g_cum, g_total.
// Also copies batch-0 durations into the duration_pred output tail.
__global__ void scan_kernel(float* __restrict__ out_tail)
{
    __shared__ int s_sum[256];
    const int tid = threadIdx.x;
    int loc[8]; int s = 0;
#pragma unroll
    for (int i = 0; i < 8; ++i) { loc[i] = (int)g_dur[tid * 8 + i]; s += loc[i]; }
    s_sum[tid] = s;
    __syncthreads();
#pragma unroll
    for (int off = 1; off < 256; off <<= 1) {
        int v = (tid >= off) ? s_sum[tid - off] : 0;
        __syncthreads();
        s_sum[tid] += v;
        __syncthreads();
    }
    int run = (tid > 0) ? s_sum[tid - 1] : 0;
#pragma unroll
    for (int i = 0; i < 8; ++i) { run += loc[i]; g_cum[tid * 8 + i] = run; }
    if (tid == 255) g_total = run;

    if (out_tail) {
        for (int i = tid; i < Tv; i += 256) out_tail[i] = g_dur[i];
    }
}

// K3: fused. First mlp_blocks blocks compute durations for batches 1..3
// (writing straight into the output tail); the rest do the expansion gather.
// MLP blocks lead the grid so their FMA work hides under the store traffic.
__global__ __launch_bounds__(NTHR)
void fused_kernel(const float* __restrict__ x, const float* __restrict__ w1,
                  const float* __restrict__ b1, const float* __restrict__ w2,
                  const float* __restrict__ b2, float* __restrict__ out,
                  long TL, long tail_off, int mlp_blocks)
{
    __shared__ float s_x[MROWS * Dv];
    __shared__ int s_idx[PPB];
    __shared__ int s_ok[PPB];
    const int tid = threadIdx.x;

    if ((int)blockIdx.x < mlp_blocks) {
        int row0 = Tv + blockIdx.x * MROWS;   // rows Tv .. Bv*Tv-1
        mlp_block(x, w1, b1, w2, b2, row0, s_x, out + tail_off);
        return;
    }

    long p0 = (long)(blockIdx.x - mlp_blocks) * PPB;
    if (tid < PPB) {
        long p = p0 + tid;
        // searchsorted(cum, p, side="right") == upper_bound
        int lo = 0, hi = Tv;
        while (lo < hi) {
            int mid = (lo + hi) >> 1;
            if ((long)g_cum[mid] <= p) lo = mid + 1; else hi = mid;
        }
        s_idx[tid] = (lo < Tv) ? lo : (Tv - 1);
        s_ok[tid]  = (p < (long)g_total);
    }
    __syncthreads();

    const float4* __restrict__ x4 = (const float4*)x;
    float4* __restrict__ out4 = (float4*)out;
    const int VD = Dv / 4;                    // 96 float4 per row
    const float4 zf = make_float4(0.f, 0.f, 0.f, 0.f);

    for (int i = tid; i < PPB * Bv * VD; i += NTHR) {
        int v  = i % VD;
        int t2 = i / VD;
        int b  = t2 & 3;
        int pl = t2 >> 2;
        long p = p0 + pl;
        if (p >= TL) continue;
        float4 val = s_ok[pl] ? x4[((long)b * Tv + s_idx[pl]) * VD + v] : zf;
        out4[((long)b * TL + p) * VD + v] = val;
    }
}

extern "C" void kernel_launch(void* const* d_in, const int* in_sizes, int n_in,
                              void* d_out, int out_size)
{
    const float* x  = (const float*)d_in[0];
    const float* w1 = (const float*)d_in[1];
    const float* b1 = (const float*)d_in[2];
    const float* w2 = (const float*)d_in[3];
    const float* b2 = (const float*)d_in[4];
    float* out = (float*)d_out;

    // Output layout: expanded (Bv, TL, Dv) then duration_pred (Bv, Tv).
    long osz = (long)out_size;
    long TL, tail_off;
    int mlp_blocks;
    if (osz % ((long)Bv * Dv) == 0) {          // no duration tail in output
        TL = osz / ((long)Bv * Dv);
        tail_off = -1;
        mlp_blocks = 0;
    } else {
        TL = (osz - (long)Bv * Tv) / ((long)Bv * Dv);
        tail_off = (long)Bv * TL * Dv;
        mlp_blocks = (Bv - 1) * Tv / MROWS;     // 384 blocks for batches 1..3
    }
    int exp_blocks = (int)((TL + PPB - 1) / PPB);

    mlp_kernel<<<Tv / MROWS, NTHR>>>(x, w1, b1, w2, b2);
    scan_kernel<<<1, 256>>>(tail_off >= 0 ? out + tail_off : nullptr);
    fused_kernel<<<mlp_blocks + exp_blocks, NTHR>>>(x, w1, b1, w2, b2, out,
                                                    TL, tail_off, mlp_blocks);
}

// round 3
// speedup vs baseline: 2.0081x; 2.0081x over previous
#include <cuda_runtime.h>
#include <math.h>
#include <stdint.h>

// Shapes fixed by the problem definition.
#define Bv 4
#define Tv 2048
#define Dv 384
#define Hv 192
#define MROWS 16      // rows per MLP block (8 warps x 2 rows)
#define KC 16         // k-tile rows (double buffered)
#define NTILE (Dv/KC) // 24
#define PPB 16        // output positions per expansion block
#define NTHR 256

// Scratch (no allocs allowed): batch-0 durations, their cumsum, total.
__device__ float g_dur[Tv];
__device__ int   g_cum[Tv];
__device__ int   g_total;

#define FMA_F32X2(d, a, b, c) \
    asm("fma.rn.f32x2 %0, %1, %2, %3;" : "=l"(d) : "l"(a), "l"(b), "l"(c))
#define PACK_DUP(out, v) \
    asm("mov.b64 %0, {%1, %1};" : "=l"(out) : "r"(v))
#define UNPACK2(lo, hi, in) \
    asm("mov.b64 {%0, %1}, %2;" : "=r"(lo), "=r"(hi) : "l"(in))

#define CP16(dst_u32, src_ptr) \
    asm volatile("cp.async.cg.shared.global [%0], [%1], 16;\n" :: "r"(dst_u32), "l"(src_ptr))
#define CP_COMMIT() asm volatile("cp.async.commit_group;\n")
#define CP_WAIT(n)  asm volatile("cp.async.wait_group %0;\n" :: "n"(n))

__device__ __forceinline__ uint32_t smem_u32(const void* p) {
    return (uint32_t)__cvta_generic_to_shared(p);
}

__device__ __forceinline__ float duration_of(float z) {
    // softplus -> clamp to MIN_DUR=8 -> round (nearest-even, matching jnp.round)
    float sp = (z > 20.f) ? z : log1pf(expf(z));
    return rintf(fmaxf(sp, 8.f));
}

// One block (256 thr, 8 warps) computes durations for MROWS=16 rows at row0.
// Warp w owns rows 2w, 2w+1. Lane owns 3 hidden j-pairs jp = lane + 32m.
// w1 streamed through smem in cp.async double-buffered KC=16 tiles;
// x tile loaded into smem once. Accumulation: packed fma.rn.f32x2.
__device__ __forceinline__ void mlp_block(
    const float* __restrict__ x, const float* __restrict__ w1,
    const float* __restrict__ b1, const float* __restrict__ w2,
    const float* __restrict__ b2, int row0,
    float* smem, float* __restrict__ dur_base)
{
    float* s_x = smem;                 // [MROWS][Dv]   24KB
    float* s_w = smem + MROWS * Dv;    // [2][KC][Hv]   24KB

    const int tid  = threadIdx.x;
    const int lane = tid & 31;
    const int warp = tid >> 5;
    const int r0 = warp * 2, r1 = r0 + 1;

    // Async-load x tile (once): 1536 float4, 6 per thread.
    {
        const float4* __restrict__ xg = (const float4*)(x + (long)row0 * Dv);
        uint32_t sx = smem_u32(s_x);
#pragma unroll
        for (int i = tid; i < MROWS * Dv / 4; i += NTHR)
            CP16(sx + (uint32_t)i * 16u, xg + i);
        CP_COMMIT();
    }
    // Prefetch w tile 0.
    {
        const float4* __restrict__ wg = (const float4*)w1;
        uint32_t sw = smem_u32(s_w);
#pragma unroll
        for (int i = tid; i < KC * Hv / 4; i += NTHR)
            CP16(sw + (uint32_t)i * 16u, wg + i);
        CP_COMMIT();
    }

    uint64_t acc0[3] = {0ull, 0ull, 0ull};
    uint64_t acc1[3] = {0ull, 0ull, 0ull};

    for (int t = 0; t < NTILE; ++t) {
        if (t + 1 < NTILE) {
            const float4* __restrict__ wg =
                (const float4*)(w1 + (long)(t + 1) * KC * Hv);
            uint32_t sw = smem_u32(s_w + ((t + 1) & 1) * KC * Hv);
#pragma unroll
            for (int i = tid; i < KC * Hv / 4; i += NTHR)
                CP16(sw + (uint32_t)i * 16u, wg + i);
            CP_COMMIT();
            CP_WAIT(1);           // x tile + w tile t complete
        } else {
            CP_WAIT(0);
        }
        __syncthreads();

        const float* wb  = s_w + (t & 1) * KC * Hv;
        const float* x0p = s_x + r0 * Dv + t * KC;
        const float* x1p = s_x + r1 * Dv + t * KC;
#pragma unroll
        for (int k0 = 0; k0 < KC; k0 += 4) {
            float4 xa0 = *(const float4*)(x0p + k0);
            float4 xa1 = *(const float4*)(x1p + k0);
#pragma unroll
            for (int kk = 0; kk < 4; ++kk) {
                uint64_t xd0, xd1;
                PACK_DUP(xd0, __float_as_uint((&xa0.x)[kk]));
                PACK_DUP(xd1, __float_as_uint((&xa1.x)[kk]));
#pragma unroll
                for (int m = 0; m < 3; ++m) {
                    uint64_t wv = *(const uint64_t*)(wb + (k0 + kk) * Hv
                                                     + 2 * (lane + 32 * m));
                    FMA_F32X2(acc0[m], xd0, wv, acc0[m]);
                    FMA_F32X2(acc1[m], xd1, wv, acc1[m]);
                }
            }
        }
        __syncthreads();
    }

    // Epilogue: bias, relu, dot with w2, warp-reduce per row.
    float bz = b2[0];
    float p0 = 0.f, p1 = 0.f;
#pragma unroll
    for (int m = 0; m < 3; ++m) {
        int jp = lane + 32 * m;
        float2 bb = *(const float2*)(b1 + 2 * jp);
        float2 ww = *(const float2*)(w2 + 2 * jp);
        uint32_t lo, hi;
        UNPACK2(lo, hi, acc0[m]);
        p0 += fmaxf(__uint_as_float(lo) + bb.x, 0.f) * ww.x
            + fmaxf(__uint_as_float(hi) + bb.y, 0.f) * ww.y;
        UNPACK2(lo, hi, acc1[m]);
        p1 += fmaxf(__uint_as_float(lo) + bb.x, 0.f) * ww.x
            + fmaxf(__uint_as_float(hi) + bb.y, 0.f) * ww.y;
    }
#pragma unroll
    for (int off = 16; off > 0; off >>= 1) {
        p0 += __shfl_xor_sync(0xffffffffu, p0, off);
        p1 += __shfl_xor_sync(0xffffffffu, p1, off);
    }
    if (lane == 0) {
        dur_base[row0 + r0] = duration_of(p0 + bz);
        dur_base[row0 + r1] = duration_of(p1 + bz);
    }
}

// K1: durations for batch 0 (rows 0..Tv) -> g_dur
__global__ __launch_bounds__(NTHR)
void mlp_kernel(const float* __restrict__ x, const float* __restrict__ w1,
                const float* __restrict__ b1, const float* __restrict__ w2,
                const float* __restrict__ b2)
{
    extern __shared__ float smem[];
    mlp_block(x, w1, b1, w2, b2, blockIdx.x * MROWS, smem, g_dur);
}

// K2: single-block inclusive scan of (int)g_dur -> g_cum, g_total.
// Also copies batch-0 durations into the duration_pred output tail.
__global__ void scan_kernel(float* __restrict__ out_tail)
{
    __shared__ int s_sum[256];
    const int tid = threadIdx.x;
    int loc[8]; int s = 0;
#pragma unroll
    for (int i = 0; i < 8; ++i) { loc[i] = (int)g_dur[tid * 8 + i]; s += loc[i]; }
    s_sum[tid] = s;
    __syncthreads();
#pragma unroll
    for (int off = 1; off < 256; off <<= 1) {
        int v = (tid >= off) ? s_sum[tid - off] : 0;
        __syncthreads();
        s_sum[tid] += v;
        __syncthreads();
    }
    int run = (tid > 0) ? s_sum[tid - 1] : 0;
#pragma unroll
    for (int i = 0; i < 8; ++i) { run += loc[i]; g_cum[tid * 8 + i] = run; }
    if (tid == 255) g_total = run;

    if (out_tail) {
        for (int i = tid; i < Tv; i += 256) out_tail[i] = g_dur[i];
    }
}

// K3: fused. First mlp_blocks blocks compute durations for batches 1..3
// (writing straight into the output tail); the rest do the expansion gather.
// MLP blocks lead the grid so their FMA work hides under the store traffic.
__global__ __launch_bounds__(NTHR)
void fused_kernel(const float* __restrict__ x, const float* __restrict__ w1,
                  const float* __restrict__ b1, const float* __restrict__ w2,
                  const float* __restrict__ b2, float* __restrict__ out,
                  long TL, long tail_off, int mlp_blocks)
{
    extern __shared__ float smem[];
    __shared__ int s_idx[PPB];
    __shared__ int s_ok[PPB];
    const int tid = threadIdx.x;

    if ((int)blockIdx.x < mlp_blocks) {
        int row0 = Tv + blockIdx.x * MROWS;   // rows Tv .. Bv*Tv-1
        mlp_block(x, w1, b1, w2, b2, row0, smem, out + tail_off);
        return;
    }

    long p0 = (long)(blockIdx.x - mlp_blocks) * PPB;
    if (tid < PPB) {
        long p = p0 + tid;
        // searchsorted(cum, p, side="right") == upper_bound
        int lo = 0, hi = Tv;
        while (lo < hi) {
            int mid = (lo + hi) >> 1;
            if ((long)g_cum[mid] <= p) lo = mid + 1; else hi = mid;
        }
        s_idx[tid] = (lo < Tv) ? lo : (Tv - 1);
        s_ok[tid]  = (p < (long)g_total);
    }
    __syncthreads();

    const float4* __restrict__ x4 = (const float4*)x;
    float4* __restrict__ out4 = (float4*)out;
    const int VD = Dv / 4;                    // 96 float4 per row
    const float4 zf = make_float4(0.f, 0.f, 0.f, 0.f);

#pragma unroll 4
    for (int i = tid; i < PPB * Bv * VD; i += NTHR) {
        int v  = i % VD;
        int t2 = i / VD;
        int b  = t2 & 3;
        int pl = t2 >> 2;
        long p = p0 + pl;
        if (p >= TL) continue;
        float4 val = s_ok[pl] ? x4[((long)b * Tv + s_idx[pl]) * VD + v] : zf;
        out4[((long)b * TL + p) * VD + v] = val;
    }
}

extern "C" void kernel_launch(void* const* d_in, const int* in_sizes, int n_in,
                              void* d_out, int out_size)
{
    const float* x  = (const float*)d_in[0];
    const float* w1 = (const float*)d_in[1];
    const float* b1 = (const float*)d_in[2];
    const float* w2 = (const float*)d_in[3];
    const float* b2 = (const float*)d_in[4];
    float* out = (float*)d_out;

    const int SMEM_DYN = (MROWS * Dv + 2 * KC * Hv) * sizeof(float); // 48KB

    static bool attr_done = false;
    if (!attr_done) {
        cudaFuncSetAttribute(mlp_kernel,
            cudaFuncAttributeMaxDynamicSharedMemorySize, SMEM_DYN);
        cudaFuncSetAttribute(fused_kernel,
            cudaFuncAttributeMaxDynamicSharedMemorySize, SMEM_DYN);
        attr_done = true;
    }

    // Output layout: expanded (Bv, TL, Dv) then duration_pred (Bv, Tv).
    long osz = (long)out_size;
    long TL, tail_off;
    int mlp_blocks;
    if (osz % ((long)Bv * Dv) == 0) {          // no duration tail in output
        TL = osz / ((long)Bv * Dv);
        tail_off = -1;
        mlp_blocks = 0;
    } else {
        TL = (osz - (long)Bv * Tv) / ((long)Bv * Dv);
        tail_off = (long)Bv * TL * Dv;
        mlp_blocks = (Bv - 1) * Tv / MROWS;     // 384 blocks for batches 1..3
    }
    int exp_blocks = (int)((TL + PPB - 1) / PPB);

    mlp_kernel<<<Tv / MROWS, NTHR, SMEM_DYN>>>(x, w1, b1, w2, b2);
    scan_kernel<<<1, 256>>>(tail_off >= 0 ? out + tail_off : nullptr);
    fused_kernel<<<mlp_blocks + exp_blocks, NTHR, SMEM_DYN>>>(x, w1, b1, w2, b2, out,
                                                              TL, tail_off, mlp_blocks);
}

// round 4
// speedup vs baseline: 2.6916x; 1.3404x over previous
#include <cuda_runtime.h>
#include <math.h>
#include <stdint.h>

// Shapes fixed by the problem definition.
#define Bv 4
#define Tv 2048
#define Dv 384
#define Hv 192
#define MROWS 32      // rows per MLP block (8 warps x 4 rows)
#define NB_MLP (Bv*Tv/MROWS)   // 256 MLP blocks cover all batches
#define KC 16         // k-tile rows (double buffered)
#define NTILE (Dv/KC) // 24
#define GMIN (8*Tv)   // guaranteed minimum total length (MIN_DUR=8)
#define PPB 16        // output positions per copy block
#define ZPB 6144      // float4 per zero block (256 thr x 24)
#define NTHR 256

// Scratch (no allocs allowed): batch-0 durations, their cumsum, total.
__device__ float g_dur[Tv];
__device__ int   g_cum[Tv];
__device__ int   g_total;

#define FMA_F32X2(d, a, b, c) \
    asm("fma.rn.f32x2 %0, %1, %2, %3;" : "=l"(d) : "l"(a), "l"(b), "l"(c))
#define PACK_DUP(out, v) \
    asm("mov.b64 %0, {%1, %1};" : "=l"(out) : "r"(v))
#define UNPACK2(lo, hi, in) \
    asm("mov.b64 {%0, %1}, %2;" : "=r"(lo), "=r"(hi) : "l"(in))

#define CP16(dst_u32, src_ptr) \
    asm volatile("cp.async.cg.shared.global [%0], [%1], 16;\n" :: "r"(dst_u32), "l"(src_ptr))
#define CP_COMMIT() asm volatile("cp.async.commit_group;\n")
#define CP_WAIT(n)  asm volatile("cp.async.wait_group %0;\n" :: "n"(n))

__device__ __forceinline__ uint32_t smem_u32(const void* p) {
    return (uint32_t)__cvta_generic_to_shared(p);
}

__device__ __forceinline__ float duration_of(float z) {
    // softplus -> clamp to MIN_DUR=8 -> round (nearest-even, matching jnp.round)
    float sp = (z > 20.f) ? z : log1pf(expf(z));
    return rintf(fmaxf(sp, 8.f));
}

// MLP for MROWS=32 rows starting at row0 (8 warps, 4 rows/warp).
// Lane owns 3 hidden j-pairs jp = lane + 32m; one LDS.64 of w feeds 4 rows
// (4 FFMA2), halving smem traffic vs 2 rows. w1 streamed via cp.async
// double-buffered KC=16 tiles; x tile loaded once.
__device__ __forceinline__ void mlp_block(
    const float* __restrict__ x, const float* __restrict__ w1,
    const float* __restrict__ b1, const float* __restrict__ w2,
    const float* __restrict__ b2, int row0,
    float* smem, float* __restrict__ out_tail)
{
    float* s_x = smem;                 // [MROWS][Dv]   48KB
    float* s_w = smem + MROWS * Dv;    // [2][KC][Hv]   24KB

    const int tid  = threadIdx.x;
    const int lane = tid & 31;
    const int warp = tid >> 5;
    const int rb   = warp * 4;

    // Async-load x tile (once): 3072 float4, 12 per thread.
    {
        const float4* __restrict__ xg = (const float4*)(x + (long)row0 * Dv);
        uint32_t sx = smem_u32(s_x);
#pragma unroll
        for (int i = tid; i < MROWS * Dv / 4; i += NTHR)
            CP16(sx + (uint32_t)i * 16u, xg + i);
        CP_COMMIT();
    }
    // Prefetch w tile 0.
    {
        const float4* __restrict__ wg = (const float4*)w1;
        uint32_t sw = smem_u32(s_w);
#pragma unroll
        for (int i = tid; i < KC * Hv / 4; i += NTHR)
            CP16(sw + (uint32_t)i * 16u, wg + i);
        CP_COMMIT();
    }

    uint64_t acc[4][3];
#pragma unroll
    for (int r = 0; r < 4; ++r)
#pragma unroll
        for (int m = 0; m < 3; ++m) acc[r][m] = 0ull;

    for (int t = 0; t < NTILE; ++t) {
        if (t + 1 < NTILE) {
            const float4* __restrict__ wg =
                (const float4*)(w1 + (long)(t + 1) * KC * Hv);
            uint32_t sw = smem_u32(s_w + ((t + 1) & 1) * KC * Hv);
#pragma unroll
            for (int i = tid; i < KC * Hv / 4; i += NTHR)
                CP16(sw + (uint32_t)i * 16u, wg + i);
            CP_COMMIT();
            CP_WAIT(1);           // x tile + w tile t complete
        } else {
            CP_WAIT(0);
        }
        __syncthreads();

        const float* wb = s_w + (t & 1) * KC * Hv;
#pragma unroll
        for (int k0 = 0; k0 < KC; k0 += 4) {
            float4 xa[4];
#pragma unroll
            for (int r = 0; r < 4; ++r)
                xa[r] = *(const float4*)(s_x + (rb + r) * Dv + t * KC + k0);
#pragma unroll
            for (int kk = 0; kk < 4; ++kk) {
                uint64_t xd[4];
#pragma unroll
                for (int r = 0; r < 4; ++r)
                    PACK_DUP(xd[r], __float_as_uint((&xa[r].x)[kk]));
#pragma unroll
                for (int m = 0; m < 3; ++m) {
                    uint64_t wv = *(const uint64_t*)(wb + (k0 + kk) * Hv
                                                     + 2 * (lane + 32 * m));
#pragma unroll
                    for (int r = 0; r < 4; ++r)
                        FMA_F32X2(acc[r][m], xd[r], wv, acc[r][m]);
                }
            }
        }
        __syncthreads();
    }

    // Epilogue: bias, relu, dot with w2, warp-reduce per row.
    float bz = b2[0];
    float pr[4] = {0.f, 0.f, 0.f, 0.f};
#pragma unroll
    for (int m = 0; m < 3; ++m) {
        int jp = lane + 32 * m;
        float2 bb = *(const float2*)(b1 + 2 * jp);
        float2 ww = *(const float2*)(w2 + 2 * jp);
#pragma unroll
        for (int r = 0; r < 4; ++r) {
            uint32_t lo, hi;
            UNPACK2(lo, hi, acc[r][m]);
            pr[r] += fmaxf(__uint_as_float(lo) + bb.x, 0.f) * ww.x
                   + fmaxf(__uint_as_float(hi) + bb.y, 0.f) * ww.y;
        }
    }
#pragma unroll
    for (int off = 16; off > 0; off >>= 1)
#pragma unroll
        for (int r = 0; r < 4; ++r)
            pr[r] += __shfl_xor_sync(0xffffffffu, pr[r], off);
    if (lane == 0) {
#pragma unroll
        for (int r = 0; r < 4; ++r) {
            int row = row0 + rb + r;
            float d = duration_of(pr[r] + bz);
            if (out_tail) out_tail[row] = d;
            if (row < Tv) g_dur[row] = d;
        }
    }
}

// K_A: blocks [0, NB_MLP) run the duration MLP for all batches; the rest
// zero-fill the expanded output for positions >= zstart (independent work
// that overlaps the MLP). Grid places MLP first so it starts in wave 1.
__global__ __launch_bounds__(NTHR)
void ka_kernel(const float* __restrict__ x, const float* __restrict__ w1,
               const float* __restrict__ b1, const float* __restrict__ w2,
               const float* __restrict__ b2, float* __restrict__ out,
               long TL, long tail_off, long zstart)
{
    extern __shared__ float smem[];
    if ((int)blockIdx.x < NB_MLP) {
        mlp_block(x, w1, b1, w2, b2, (int)blockIdx.x * MROWS, smem,
                  tail_off >= 0 ? out + tail_off : nullptr);
        return;
    }

    // Zero-fill: flat float4 index space over 4 slabs out[b][zstart..TL][:].
    unsigned S = (unsigned)((TL - zstart) * (Dv / 4));   // f4 per slab
    unsigned total = S * Bv;
    unsigned f0 = (unsigned)(blockIdx.x - NB_MLP) * ZPB;
    if (f0 >= total) return;
    float4* __restrict__ out4 = (float4*)out;
    const float4 zf = make_float4(0.f, 0.f, 0.f, 0.f);
    const int tid = threadIdx.x;

    unsigned bA = f0 / S, bB = (min(f0 + ZPB, total) - 1) / S;
    if (bA == bB) {  // fast path: whole block inside one slab
        float4* base = out4 + ((long)bA * TL + zstart) * (Dv / 4) - (long)bA * S;
#pragma unroll
        for (int it = 0; it < ZPB / NTHR; ++it) {
            unsigned f = f0 + tid + it * NTHR;
            if (f < total) base[f] = zf;
        }
    } else {
#pragma unroll
        for (int it = 0; it < ZPB / NTHR; ++it) {
            unsigned f = f0 + tid + it * NTHR;
            if (f >= total) break;
            unsigned b = f / S, o = f - b * S;
            out4[((long)b * TL + zstart) * (Dv / 4) + o] = zf;
        }
    }
}

// K_scan: single-block inclusive scan of (int)g_dur -> g_cum, g_total.
__global__ void scan_kernel()
{
    __shared__ int s_sum[256];
    const int tid = threadIdx.x;
    int loc[8]; int s = 0;
#pragma unroll
    for (int i = 0; i < 8; ++i) { loc[i] = (int)g_dur[tid * 8 + i]; s += loc[i]; }
    s_sum[tid] = s;
    __syncthreads();
#pragma unroll
    for (int off = 1; off < 256; off <<= 1) {
        int v = (tid >= off) ? s_sum[tid - off] : 0;
        __syncthreads();
        s_sum[tid] += v;
        __syncthreads();
    }
    int run = (tid > 0) ? s_sum[tid - 1] : 0;
#pragma unroll
    for (int i = 0; i < 8; ++i) { run += loc[i]; g_cum[tid * 8 + i] = run; }
    if (tid == 255) g_total = run;
}

// K_B: gather-copy for valid positions p < g_total. Positions >= g_total
// already hold zeros from K_A (in-stream kernel order makes the overwrite
// of [zstart, g_total) race-free). Blocks entirely past g_total exit.
__global__ __launch_bounds__(NTHR)
void kb_kernel(const float* __restrict__ x, float* __restrict__ out, long TL)
{
    __shared__ int s_idx[PPB];
    __shared__ int s_ok[PPB];
    const int tid = threadIdx.x;
    long p0 = (long)blockIdx.x * PPB;
    int total = g_total;
    if (p0 >= (long)total) return;

    if (tid < PPB) {
        long p = p0 + tid;
        // searchsorted(cum, p, side="right") == upper_bound
        int lo = 0, hi = Tv;
        while (lo < hi) {
            int mid = (lo + hi) >> 1;
            if ((long)g_cum[mid] <= p) lo = mid + 1; else hi = mid;
        }
        s_idx[tid] = (lo < Tv) ? lo : (Tv - 1);
        s_ok[tid]  = (p < (long)total) && (p < TL);
    }
    __syncthreads();

    const float4* __restrict__ x4 = (const float4*)x;
    float4* __restrict__ out4 = (float4*)out;
    const int VD = Dv / 4;                    // 96 float4 per row

#pragma unroll 4
    for (int i = tid; i < PPB * Bv * VD; i += NTHR) {
        int v  = i % VD;
        int t2 = i / VD;
        int b  = t2 & 3;
        int pl = t2 >> 2;
        if (!s_ok[pl]) continue;
        long p = p0 + pl;
        out4[((long)b * TL + p) * VD + v] = x4[((long)b * Tv + s_idx[pl]) * VD + v];
    }
}

extern "C" void kernel_launch(void* const* d_in, const int* in_sizes, int n_in,
                              void* d_out, int out_size)
{
    const float* x  = (const float*)d_in[0];
    const float* w1 = (const float*)d_in[1];
    const float* b1 = (const float*)d_in[2];
    const float* w2 = (const float*)d_in[3];
    const float* b2 = (const float*)d_in[4];
    float* out = (float*)d_out;

    const int SMEM_DYN = (MROWS * Dv + 2 * KC * Hv) * sizeof(float); // 72KB

    static bool attr_done = false;
    if (!attr_done) {
        cudaFuncSetAttribute(ka_kernel,
            cudaFuncAttributeMaxDynamicSharedMemorySize, SMEM_DYN);
        attr_done = true;
    }

    // Output layout: expanded (Bv, TL, Dv) then duration_pred (Bv, Tv).
    long osz = (long)out_size;
    long TL, tail_off;
    if (osz % ((long)Bv * Dv) == 0) {          // no duration tail in output
        TL = osz / ((long)Bv * Dv);
        tail_off = -1;
    } else {
        TL = (osz - (long)Bv * Tv) / ((long)Bv * Dv);
        tail_off = (long)Bv * TL * Dv;
    }
    long zstart = (long)GMIN < TL ? (long)GMIN : TL;  // zeros for p >= zstart

    long zf4 = (TL - zstart) * (Dv / 4) * Bv;          // float4 to zero
    int nb_zero = (int)((zf4 + ZPB - 1) / ZPB);
    int nb_copy = (int)((TL + PPB - 1) / PPB);

    ka_kernel<<<NB_MLP + nb_zero, NTHR, SMEM_DYN>>>(x, w1, b1, w2, b2, out,
                                                    TL, tail_off, zstart);
    scan_kernel<<<1, 256>>>();
    kb_kernel<<<nb_copy, NTHR>>>(x, out, TL);
}